// round 17
// baseline (speedup 1.0000x reference)
#include <cuda_runtime.h>
#include <cuda_bf16.h>
#include <stdint.h>

#define BN_EPS 1e-5f
#define KPAD 544            // 512 (h) + 16 (hrelu) + 16 zero pad; 17 stages of 32
#define NSTG 17

// ------------- device scratch (no allocations allowed) -------------
__device__ __nv_bfloat16 g_hA[2][2048 * KPAD];   // A operand [b][k]; k 0..511 = h, 512..527 = hrelu, 528..543 = 0
__device__ float         g_c[2048 * 512];        // cell state [b][j]
__device__ float         g_lp[2][2048 * 2];
__device__ __nv_bfloat16 g_Beff[2048 * KPAD];    // fused B [n'][k], n' = 4j+q
__device__ float         g_cb[2048];             // fused gate bias
__device__ float         g_A1[32];               // folded se layer1 [2][16]
__device__ float         g_B1[16];
__device__ float         g_hpw1f[8192];          // folded hp layer1 [512][16] fp32
__device__ float         g_hpb1f[16];

// ------------- helpers -------------
__device__ __forceinline__ float sigf(float x) { return 1.f / (1.f + __expf(-x)); }

__device__ __forceinline__ void cp16(void* s, const void* g) {
    uint32_t sa = (uint32_t)__cvta_generic_to_shared(s);
    asm volatile("cp.async.cg.shared.global [%0], [%1], 16;\n" :: "r"(sa), "l"(g) : "memory");
}
__device__ __forceinline__ void ldsm4(uint32_t* r, const void* p) {
    uint32_t a = (uint32_t)__cvta_generic_to_shared(p);
    asm volatile("ldmatrix.sync.aligned.m8n8.x4.shared.b16 {%0,%1,%2,%3}, [%4];\n"
                 : "=r"(r[0]), "=r"(r[1]), "=r"(r[2]), "=r"(r[3]) : "r"(a));
}
__device__ __forceinline__ void ldsm2(uint32_t* r, const void* p) {
    uint32_t a = (uint32_t)__cvta_generic_to_shared(p);
    asm volatile("ldmatrix.sync.aligned.m8n8.x2.shared.b16 {%0,%1}, [%2];\n"
                 : "=r"(r[0]), "=r"(r[1]) : "r"(a));
}
__device__ __forceinline__ void mma16(float* c, const uint32_t* a, const uint32_t* b) {
    asm volatile(
        "mma.sync.aligned.m16n8k16.row.col.f32.bf16.bf16.f32 "
        "{%0,%1,%2,%3},{%4,%5,%6,%7},{%8,%9},{%0,%1,%2,%3};\n"
        : "+f"(c[0]), "+f"(c[1]), "+f"(c[2]), "+f"(c[3])
        : "r"(a[0]), "r"(a[1]), "r"(a[2]), "r"(a[3]), "r"(b[0]), "r"(b[1]));
}

// ------------- prep kernels (run every launch, deterministic) -------------
__global__ void prep_fold(const float* se_w1, const float* se_b1, const float* se_g,
                          const float* se_bt, const float* se_m, const float* se_v,
                          const float* hp_w1, const float* hp_b1, const float* hp_g,
                          const float* hp_bt, const float* hp_m, const float* hp_v) {
    __shared__ float s2s[16];
    int t = threadIdx.x;
    if (t < 16) {
        float s = se_g[t] * rsqrtf(se_v[t] + BN_EPS);
        g_A1[t]      = se_w1[t] * s;
        g_A1[16 + t] = se_w1[16 + t] * s;
        g_B1[t]      = (se_b1[t] - se_m[t]) * s + se_bt[t];
        float s2 = hp_g[t] * rsqrtf(hp_v[t] + BN_EPS);
        s2s[t] = s2;
        g_hpb1f[t] = (hp_b1[t] - hp_m[t]) * s2 + hp_bt[t];
    }
    __syncthreads();
    for (int i = t; i < 8192; i += 256) g_hpw1f[i] = hp_w1[i] * s2s[i & 15];
}

// Beff[n'][k], k 0..511: w_hh rows, gate-interleaved n' = 4j+q
__global__ void prep_whh(const float* __restrict__ w_hh) {
    int id = blockIdx.x * 256 + threadIdx.x;          // 1048576 threads
    int np = id >> 9, k = id & 511;
    int j = np >> 2, q = np & 3;
    g_Beff[(size_t)np * KPAD + k] = __float2bfloat16(w_hh[(size_t)(q * 512 + j) * 512 + k]);
}

// Beff k 512..527: Wse[jj][n'] = sum_e se_w2[jj][e] * w_ih[n][e]
__global__ void prep_wse(const float* __restrict__ se_w2, const float* __restrict__ w_ih) {
    int id = blockIdx.x * 256 + threadIdx.x;          // 32768 threads
    int jj = id & 15, np = id >> 4;
    int j = np >> 2, q = np & 3;
    const float4* wr = (const float4*)(w_ih + (size_t)(q * 512 + j) * 512);
    const float4* sw = (const float4*)(se_w2 + (size_t)jj * 512);
    float acc = 0.f;
#pragma unroll 4
    for (int e = 0; e < 128; e++) {
        float4 a = wr[e], b = sw[e];
        acc += a.x * b.x + a.y * b.y + a.z * b.z + a.w * b.w;
    }
    g_Beff[(size_t)np * KPAD + 512 + jj] = __float2bfloat16(acc);
}

// fused bias + zero Beff k-pad 528..543
__global__ void prep_cb(const float* __restrict__ se_b2, const float* __restrict__ w_ih,
                        const float* __restrict__ b_ih, const float* __restrict__ b_hh) {
    int np = blockIdx.x * 256 + threadIdx.x;          // 2048 threads
    int j = np >> 2, q = np & 3;
    int n = q * 512 + j;
    const float4* wr = (const float4*)(w_ih + (size_t)n * 512);
    const float4* sb = (const float4*)se_b2;
    float acc = b_ih[n] + b_hh[n];
#pragma unroll 4
    for (int e = 0; e < 128; e++) {
        float4 a = wr[e], b = sb[e];
        acc += a.x * b.x + a.y * b.y + a.z * b.z + a.w * b.w;
    }
    g_cb[np] = acc;
#pragma unroll
    for (int i = 0; i < 16; i++)
        g_Beff[(size_t)np * KPAD + 528 + i] = __float2bfloat16(0.f);
}

// h0 -> g_hA[0] (bf16), c0 -> g_c (copy), zero k-pads of both hA buffers
__global__ void init_hc(const float* __restrict__ hh, const float* __restrict__ ch) {
    int id = blockIdx.x * 256 + threadIdx.x;          // 2162688 threads
    if (id < 1048576) {
        int b = id >> 9, j = id & 511;
        g_hA[0][(size_t)b * KPAD + j] = __float2bfloat16(hh[id]);
    } else if (id < 2097152) {
        g_c[id - 1048576] = ch[id - 1048576];
    } else {
        int p = id - 2097152;                          // 0..65535
        int buf = p >> 15, r = p & 32767;
        int b = r >> 4, jj = r & 15;
        g_hA[buf][(size_t)b * KPAD + 528 + jj] = __float2bfloat16(0.f);
    }
}

// lp0 copy + hrelu(lp0) -> g_hA[0] k 512..527
__global__ void init_front(const float* __restrict__ last_pos) {
    int b = blockIdx.x * 256 + threadIdx.x;           // 2048 threads
    float l0 = last_pos[b * 2], l1 = last_pos[b * 2 + 1];
    g_lp[0][b * 2] = l0; g_lp[0][b * 2 + 1] = l1;
#pragma unroll
    for (int jj = 0; jj < 16; jj++)
        g_hA[0][(size_t)b * KPAD + 512 + jj] =
            __float2bfloat16(fmaxf(l0 * g_A1[jj] + l1 * g_A1[16 + jj] + g_B1[jj], 0.f));
}

// ------------- per-step GEMM + fused LSTM cell -------------
// gates[b][n'] = sum_k hA[b][k] * Beff[n'][k] + cb[n']
__global__ void __launch_bounds__(256, 2) gemm_lstm(int cur) {
    __shared__ __align__(16) uint16_t As[2][128][40];  // row pad 40 bf16 (80B): ldmatrix conflict-free
    __shared__ __align__(16) uint16_t Bs[2][128][40];
    const __nv_bfloat16* Ag = g_hA[cur];
    __nv_bfloat16* Hn = g_hA[cur ^ 1];
    int tid = threadIdx.x;
    int bm = blockIdx.y * 128, bn = blockIdx.x * 128;
    int lane = tid & 31, wid = tid >> 5;
    int wm = wid & 3, wn = wid >> 2;                   // warp tile: 32 m x 64 n
    int tig = lane & 3, grp = lane >> 2;

    float acc[2][8][4];
#pragma unroll
    for (int a = 0; a < 2; a++)
#pragma unroll
        for (int b = 0; b < 8; b++)
#pragma unroll
            for (int c = 0; c < 4; c++) acc[a][b][c] = 0.f;

    auto load = [&](int st, int buf) {
        int k0 = st * 32;
#pragma unroll
        for (int i = 0; i < 2; i++) {
            int c = tid + i * 256;
            int row = c >> 2, seg = c & 3;
            cp16(&As[buf][row][seg * 8], Ag + (size_t)(bm + row) * KPAD + k0 + seg * 8);
            cp16(&Bs[buf][row][seg * 8], g_Beff + (size_t)(bn + row) * KPAD + k0 + seg * 8);
        }
    };

    load(0, 0);
    asm volatile("cp.async.commit_group;\n" ::: "memory");
    int buf = 0;
    // ldmatrix lane addressing (computed once)
    int arow = wm * 32 + (lane & 15);                  // + mt*16
    int akc  = ((lane >> 4) & 1) << 3;                 // + k16
    int brow = wn * 64 + (lane & 7);                   // + nt*8
    int bkc  = ((lane >> 3) & 1) << 3;                 // + k16

    for (int st = 0; st < NSTG; st++) {
        if (st + 1 < NSTG) load(st + 1, buf ^ 1);
        asm volatile("cp.async.commit_group;\n" ::: "memory");
        asm volatile("cp.async.wait_group 1;\n" ::: "memory");
        __syncthreads();
#pragma unroll
        for (int k16 = 0; k16 < 32; k16 += 16) {
            uint32_t af[2][4], bf[8][2];
#pragma unroll
            for (int mt = 0; mt < 2; mt++)
                ldsm4(af[mt], &As[buf][arow + mt * 16][akc + k16]);
#pragma unroll
            for (int nt = 0; nt < 8; nt++)
                ldsm2(bf[nt], &Bs[buf][brow + nt * 8][bkc + k16]);
#pragma unroll
            for (int mt = 0; mt < 2; mt++)
#pragma unroll
                for (int nt = 0; nt < 8; nt++) mma16(acc[mt][nt], af[mt], bf[nt]);
        }
        __syncthreads();
        buf ^= 1;
    }

    // epilogue: lane pairs hold (i,f)/(g,o) of the same unit j (same C layout as before)
#pragma unroll
    for (int mt = 0; mt < 2; mt++) {
        int r0 = bm + wm * 32 + mt * 16 + grp;         // batch index
#pragma unroll
        for (int nt = 0; nt < 8; nt++) {
            int col = bn + wn * 64 + nt * 8 + 2 * tig;
            float cb0 = g_cb[col], cb1 = g_cb[col + 1];
            float c0 = acc[mt][nt][0] + cb0;
            float c1 = acc[mt][nt][1] + cb1;
            float c2 = acc[mt][nt][2] + cb0;
            float c3 = acc[mt][nt][3] + cb1;
            float p0 = __shfl_xor_sync(0xffffffffu, c0, 1);
            float p1 = __shfl_xor_sync(0xffffffffu, c1, 1);
            float p2 = __shfl_xor_sync(0xffffffffu, c2, 1);
            float p3 = __shfl_xor_sync(0xffffffffu, c3, 1);
            if (!(lane & 1)) {                          // even lane owns (i,f); partner sent (g,o)
                int j = col >> 2;
                float i0 = sigf(c0), f0 = sigf(c1), g0 = tanhf(p0), o0 = sigf(p1);
                float cc = g_c[(size_t)r0 * 512 + j];
                cc = f0 * cc + i0 * g0;
                g_c[(size_t)r0 * 512 + j] = cc;
                Hn[(size_t)r0 * KPAD + j] = __float2bfloat16(o0 * tanhf(cc));
                float i1 = sigf(c2), f1 = sigf(c3), g1 = tanhf(p2), o1 = sigf(p3);
                float cd = g_c[(size_t)(r0 + 8) * 512 + j];
                cd = f1 * cd + i1 * g1;
                g_c[(size_t)(r0 + 8) * 512 + j] = cd;
                Hn[(size_t)(r0 + 8) * KPAD + j] = __float2bfloat16(o1 * tanhf(cd));
            }
        }
    }
}

// ------------- per-step pos head + next-step front MLP -------------
// 4 threads per batch, each covers 128 j; float4 w1 broadcasts from smem; shfl reduce.
__global__ void __launch_bounds__(256) posse(int s, const float* __restrict__ hp_w2,
                                             const float* __restrict__ hp_b2, float* outp) {
    __shared__ __align__(16) float w1s[8192];          // [j][16]
    int tid = threadIdx.x;
    {
        const float4* src = (const float4*)g_hpw1f;
        float4* dst = (float4*)w1s;
        for (int i = tid; i < 2048; i += 256) dst[i] = src[i];
    }
    __syncthreads();

    int nxt = (s & 1) ^ 1;
    const __nv_bfloat16* hAn = g_hA[nxt];
    const float* lpc = g_lp[s & 1];
    float* lpn = g_lp[nxt];
    __nv_bfloat16* hAw = g_hA[nxt];

    int gid = blockIdx.x * 256 + tid;                  // 8192 threads
    int b = gid >> 2, q = gid & 3;

    float4 a0 = {0,0,0,0}, a1 = {0,0,0,0}, a2 = {0,0,0,0}, a3 = {0,0,0,0};
    const uint4* hp = (const uint4*)(hAn + (size_t)b * KPAD + q * 128);
#pragma unroll 4
    for (int it = 0; it < 16; it++) {
        uint4 v = hp[it];
        uint32_t wv[4] = {v.x, v.y, v.z, v.w};
#pragma unroll
        for (int e = 0; e < 8; e++) {
            __nv_bfloat16 hb = ((const __nv_bfloat16*)wv)[e];
            float hj = __bfloat162float(hb);
            int j = q * 128 + it * 8 + e;
            const float4* wr = (const float4*)&w1s[j * 16];
            float4 w0 = wr[0], w1 = wr[1], w2 = wr[2], w3 = wr[3];
            a0.x += hj * w0.x; a0.y += hj * w0.y; a0.z += hj * w0.z; a0.w += hj * w0.w;
            a1.x += hj * w1.x; a1.y += hj * w1.y; a1.z += hj * w1.z; a1.w += hj * w1.w;
            a2.x += hj * w2.x; a2.y += hj * w2.y; a2.z += hj * w2.z; a2.w += hj * w2.w;
            a3.x += hj * w3.x; a3.y += hj * w3.y; a3.z += hj * w3.z; a3.w += hj * w3.w;
        }
    }
    // reduce across the 4 q-threads (lanes differ in bits 0..1)
    float acc[16] = {a0.x,a0.y,a0.z,a0.w, a1.x,a1.y,a1.z,a1.w,
                     a2.x,a2.y,a2.z,a2.w, a3.x,a3.y,a3.z,a3.w};
#pragma unroll
    for (int jj = 0; jj < 16; jj++) {
        acc[jj] += __shfl_xor_sync(0xffffffffu, acc[jj], 1);
        acc[jj] += __shfl_xor_sync(0xffffffffu, acc[jj], 2);
    }
    if (q == 0) {
        float pr0 = hp_b2[0], pr1 = hp_b2[1];
#pragma unroll
        for (int jj = 0; jj < 16; jj++) {
            float v = fmaxf(acc[jj] + g_hpb1f[jj], 0.f);
            pr0 += v * hp_w2[jj * 2];
            pr1 += v * hp_w2[jj * 2 + 1];
        }
        float l0 = lpc[b * 2], l1 = lpc[b * 2 + 1];
        float n0 = sigf(pr0 + l0), n1 = sigf(pr1 + l1);
        lpn[b * 2] = n0; lpn[b * 2 + 1] = n1;
        outp[b * 2] = n0; outp[b * 2 + 1] = n1;
#pragma unroll
        for (int jj = 0; jj < 16; jj++)
            hAw[(size_t)b * KPAD + 512 + jj] =
                __float2bfloat16(fmaxf(n0 * g_A1[jj] + n1 * g_A1[16 + jj] + g_B1[jj], 0.f));
    }
}

// ------------- launch -------------
extern "C" void kernel_launch(void* const* d_in, const int* in_sizes, int n_in,
                              void* d_out, int out_size) {
    const float* last_pos = (const float*)d_in[0];
    const float* hh    = (const float*)d_in[1];
    const float* ch    = (const float*)d_in[2];
    const float* se_w1 = (const float*)d_in[3];
    const float* se_b1 = (const float*)d_in[4];
    const float* se_g  = (const float*)d_in[5];
    const float* se_bt = (const float*)d_in[6];
    const float* se_m  = (const float*)d_in[7];
    const float* se_v  = (const float*)d_in[8];
    const float* se_w2 = (const float*)d_in[9];
    const float* se_b2 = (const float*)d_in[10];
    const float* w_ih  = (const float*)d_in[11];
    const float* w_hh  = (const float*)d_in[12];
    const float* b_ih  = (const float*)d_in[13];
    const float* b_hh  = (const float*)d_in[14];
    const float* hp_w1 = (const float*)d_in[15];
    const float* hp_b1 = (const float*)d_in[16];
    const float* hp_g  = (const float*)d_in[17];
    const float* hp_bt = (const float*)d_in[18];
    const float* hp_m  = (const float*)d_in[19];
    const float* hp_v  = (const float*)d_in[20];
    const float* hp_w2 = (const float*)d_in[21];
    const float* hp_b2 = (const float*)d_in[22];
    float* out = (float*)d_out;

    prep_fold<<<1, 256>>>(se_w1, se_b1, se_g, se_bt, se_m, se_v,
                          hp_w1, hp_b1, hp_g, hp_bt, hp_m, hp_v);
    prep_whh<<<4096, 256>>>(w_hh);
    prep_wse<<<128, 256>>>(se_w2, w_ih);
    prep_cb<<<8, 256>>>(se_b2, w_ih, b_ih, b_hh);
    init_hc<<<8448, 256>>>(hh, ch);
    init_front<<<8, 256>>>(last_pos);

    for (int s = 0; s < 32; s++) {
        gemm_lstm<<<dim3(16, 16), 256>>>(s & 1);
        posse<<<32, 256>>>(s, hp_w2, hp_b2, out + (size_t)s * 4096);
    }
}